// round 14
// baseline (speedup 1.0000x reference)
#include <cuda_runtime.h>
#include <cuda_fp16.h>
#include <cstdint>

#define Bb  2
#define Ls  4096
#define Ds  512
#define Hh  8
#define HDs 64
#define FFs 2048
#define WIN 128
#define Ms  (Bb*Ls)
#define QS  1536     // fused qkv row stride (q|k|v) in halves

// ---------------- scratch (device globals: allocation-guard safe) ----------
__device__ __half g_xh  [Ms*Ds];
__device__ __half g_qkv [Ms*QS];
__device__ __half g_att [Ms*Ds];
__device__ float  g_prj [Ms*Ds];
__device__ float  g_h   [Ms*Ds];
__device__ __half g_hr  [Ms*Ds];
__device__ __half g_ff1 [Ms*FFs];
__device__ float  g_ff2 [Ms*Ds];
__device__ __half g_wqkvt[3*Ds*Ds];
__device__ __half g_wot [Ds*Ds];
__device__ __half g_w1t [Ds*FFs];
__device__ __half g_w2t [FFs*Ds];
__device__ float  g_bqkv[QS];

// ---------------- helpers ---------------------------------------------------
__device__ __forceinline__ void cp16(uint32_t dst_smem, const void* src) {
    asm volatile("cp.async.ca.shared.global [%0], [%1], 16;\n"
                 :: "r"(dst_smem), "l"(src));
}
#define CP_COMMIT() asm volatile("cp.async.commit_group;\n")
#define CP_WAIT(n)  asm volatile("cp.async.wait_group %0;\n" :: "n"(n))

__device__ __forceinline__ uint32_t f2tf(float x) {
    uint32_t u;
    asm("cvt.rna.tf32.f32 %0, %1;" : "=r"(u) : "f"(x));
    return u;
}
__device__ __forceinline__ float rna(float x) { return __uint_as_float(f2tf(x)); }

__device__ __forceinline__ void mma_f16(float d[4],
    uint32_t a0, uint32_t a1, uint32_t a2, uint32_t a3, uint32_t b0, uint32_t b1)
{
    asm volatile(
        "mma.sync.aligned.m16n8k16.row.col.f32.f16.f16.f32 "
        "{%0,%1,%2,%3}, {%4,%5,%6,%7}, {%8,%9}, {%0,%1,%2,%3};\n"
        : "+f"(d[0]), "+f"(d[1]), "+f"(d[2]), "+f"(d[3])
        : "r"(a0), "r"(a1), "r"(a2), "r"(a3), "r"(b0), "r"(b1));
}

__device__ __forceinline__ void ldsm_x4(uint32_t r[4], uint32_t addr)
{
    asm volatile("ldmatrix.sync.aligned.m8n8.x4.shared.b16 {%0,%1,%2,%3}, [%4];"
                 : "=r"(r[0]), "=r"(r[1]), "=r"(r[2]), "=r"(r[3]) : "r"(addr));
}
__device__ __forceinline__ void ldsm_x4_trans(uint32_t& r0, uint32_t& r1,
                                              uint32_t& r2, uint32_t& r3, uint32_t addr)
{
    asm volatile("ldmatrix.sync.aligned.m8n8.x4.trans.shared.b16 {%0,%1,%2,%3}, [%4];"
                 : "=r"(r0), "=r"(r1), "=r"(r2), "=r"(r3) : "r"(addr));
}

// ================= prologue kernels =========================================
__global__ __launch_bounds__(256)
void to_half(const float* __restrict__ in, __half* __restrict__ o, int n4)
{
    int i = blockIdx.x * blockDim.x + threadIdx.x;
    if (i < n4) {
        float4 t = ((const float4*)in)[i];
        __half2 lo = __floats2half2_rn(t.x, t.y);
        __half2 hi = __floats2half2_rn(t.z, t.w);
        ((uint2*)o)[i] = make_uint2(*(uint32_t*)&lo, *(uint32_t*)&hi);
    }
}

// all six W[K][N] -> Wt[N][K] (half) in one launch
__global__ __launch_bounds__(256)
void transpose_all(const float* __restrict__ Wq, const float* __restrict__ Wk,
                   const float* __restrict__ Wv, const float* __restrict__ Wo,
                   const float* __restrict__ W1, const float* __restrict__ W2,
                   __half* __restrict__ wqkvt, __half* __restrict__ wot,
                   __half* __restrict__ w1t,   __half* __restrict__ w2t)
{
    const int bid = blockIdx.x;
    const float* W; __half* Wt; int K, N, tile;
    if      (bid < 256)  { W = Wq; Wt = wqkvt;               K = Ds;  N = Ds;  tile = bid; }
    else if (bid < 512)  { W = Wk; Wt = wqkvt + Ds * Ds;     K = Ds;  N = Ds;  tile = bid - 256; }
    else if (bid < 768)  { W = Wv; Wt = wqkvt + 2 * Ds * Ds; K = Ds;  N = Ds;  tile = bid - 512; }
    else if (bid < 1024) { W = Wo; Wt = wot;                 K = Ds;  N = Ds;  tile = bid - 768; }
    else if (bid < 2048) { W = W1; Wt = w1t;                 K = Ds;  N = FFs; tile = bid - 1024; }
    else                 { W = W2; Wt = w2t;                 K = FFs; N = Ds;  tile = bid - 2048; }
    const int ntx = N / 32;
    const int nx = (tile % ntx) * 32, ky = (tile / ntx) * 32;

    __shared__ float t[32][33];
    const int x = threadIdx.x, y = threadIdx.y;
#pragma unroll
    for (int j = 0; j < 32; j += 8)
        t[y + j][x] = W[(size_t)(ky + y + j) * N + nx + x];
    __syncthreads();
#pragma unroll
    for (int j = 0; j < 32; j += 8)
        Wt[(size_t)(nx + y + j) * K + ky + x] = __float2half(t[x][y + j]);
}

__global__ void concat3(const float* __restrict__ a, const float* __restrict__ b,
                        const float* __restrict__ c, float* __restrict__ o)
{
    int i = blockIdx.x * blockDim.x + threadIdx.x;
    o[i] = (i < Ds) ? a[i] : (i < 2 * Ds) ? b[i - Ds] : c[i - 2 * Ds];
}

// ================= fp16 tensor-core GEMM (round-10 best) ====================
// C[M,N] = A[M,K] @ Bt[N,K]^T + bias.
// 256 thr, CTA tile 128x256x64, warp grid 2x4, warp tile 64x64.
// 3-stage cp.async pipeline, ldmatrix fragment loads.
// out_mode: 0 = fp32, 1 = fp32 rna-rounded, 2 = half
#define HST    72
#define HAS    (128 * HST)
#define HBS    (256 * HST)
#define HSTG   (HAS + HBS)
#define HG_SMEM (3 * HSTG * 2)

__global__ __launch_bounds__(256, 1)
void hgemm(const __half* __restrict__ A, const __half* __restrict__ Bt,
           const float* __restrict__ bias, void* __restrict__ Cv,
           int M, int N, int K, int relu, int out_mode)
{
    extern __shared__ __align__(256) __half sh[];
    const uint32_t sb = (uint32_t)__cvta_generic_to_shared(sh);

    const int tid  = threadIdx.x;
    const int lane = tid & 31;
    const int warp = tid >> 5;
    const int gid  = lane >> 2;
    const int tg   = lane & 3;
    const int wm   = (warp >> 2) * 64;
    const int wn   = (warp & 3) * 64;
    const int bm   = blockIdx.y * 128;
    const int bn   = blockIdx.x * 256;

    const int ar = tid >> 3;
    const int ac = (tid & 7) * 8;

    const int a_row = wm + ((lane >> 3) & 1) * 8 + (lane & 7);
    const int a_k   = ((lane >> 4) & 1) * 8;
    const int b_row = wn + ((lane >> 4) & 1) * 8 + (lane & 7);
    const int b_k   = ((lane >> 3) & 1) * 8;

    float d[4][8][4];
#pragma unroll
    for (int i = 0; i < 4; i++)
#pragma unroll
        for (int j = 0; j < 8; j++)
#pragma unroll
            for (int c = 0; c < 4; c++) d[i][j][c] = 0.f;

    auto do_load = [&](int stage, int k0) {
        const __half* pa = A  + (size_t)(bm + ar) * K + k0 + ac;
        const __half* pb = Bt + (size_t)(bn + ar) * K + k0 + ac;
        const uint32_t ba = sb + (uint32_t)stage * (HSTG * 2);
        const uint32_t bb = ba + HAS * 2;
#pragma unroll
        for (int i = 0; i < 4; i++) {
            uint32_t off = (uint32_t)((ar + 32 * i) * HST + ac) * 2;
            cp16(ba + off, pa + (size_t)32 * i * K);
        }
#pragma unroll
        for (int i = 0; i < 8; i++) {
            uint32_t off = (uint32_t)((ar + 32 * i) * HST + ac) * 2;
            cp16(bb + off, pb + (size_t)32 * i * K);
        }
    };

    const int T = K / 64;
    do_load(0, 0);
    CP_COMMIT();
    if (T > 1) { do_load(1, 64); CP_COMMIT(); }

    for (int t = 0; t < T; t++) {
        if (t + 1 < T) { CP_WAIT(1); } else { CP_WAIT(0); }
        __syncthreads();

        const int buf = t % 3;
        const uint32_t sA = sb + (uint32_t)buf * (HSTG * 2);
        const uint32_t sB = sA + HAS * 2;

#pragma unroll
        for (int kc = 0; kc < 4; kc++) {
            const int kk = kc * 16;
            uint32_t af[4][4], bf[4][4];
#pragma unroll
            for (int im = 0; im < 4; im++)
                ldsm_x4(af[im], sA + (uint32_t)((a_row + im * 16) * HST + kk + a_k) * 2);
#pragma unroll
            for (int jp = 0; jp < 4; jp++)
                ldsm_x4(bf[jp], sB + (uint32_t)((b_row + jp * 16) * HST + kk + b_k) * 2);
#pragma unroll
            for (int im = 0; im < 4; im++)
#pragma unroll
                for (int jn = 0; jn < 8; jn++)
                    mma_f16(d[im][jn], af[im][0], af[im][1], af[im][2], af[im][3],
                            bf[jn >> 1][(jn & 1) * 2], bf[jn >> 1][(jn & 1) * 2 + 1]);
        }

        if (t + 2 < T) { do_load((t + 2) % 3, (t + 2) * 64); CP_COMMIT(); }
    }

    // epilogue
#pragma unroll
    for (int jn = 0; jn < 8; jn++) {
        const int col = bn + wn + jn * 8 + 2 * tg;
        float2 bv = *(const float2*)&bias[col];
#pragma unroll
        for (int im = 0; im < 4; im++) {
            const int row = bm + wm + im * 16 + gid;
            float v0 = d[im][jn][0] + bv.x, v1 = d[im][jn][1] + bv.y;
            float v2 = d[im][jn][2] + bv.x, v3 = d[im][jn][3] + bv.y;
            if (relu) {
                v0 = fmaxf(v0, 0.f); v1 = fmaxf(v1, 0.f);
                v2 = fmaxf(v2, 0.f); v3 = fmaxf(v3, 0.f);
            }
            if (out_mode == 2) {
                __half* Ch = (__half*)Cv;
                *(__half2*)&Ch[(size_t)row       * N + col] = __floats2half2_rn(v0, v1);
                *(__half2*)&Ch[(size_t)(row + 8) * N + col] = __floats2half2_rn(v2, v3);
            } else {
                if (out_mode == 1) { v0 = rna(v0); v1 = rna(v1); v2 = rna(v2); v3 = rna(v3); }
                float* Cf = (float*)Cv;
                *(float2*)&Cf[(size_t)row       * N + col] = make_float2(v0, v1);
                *(float2*)&Cf[(size_t)(row + 8) * N + col] = make_float2(v2, v3);
            }
        }
    }
}

// ============== banded attention, fp16 mma, q-tile 128 ======================
// 256 threads (8 warps x 16 query rows). Smem: QP[128][72], K[64][72], V[64][72]
#define AST 72
#define AQ_ROWS 128
#define OFF_KT  (AQ_ROWS * AST)            // K tile offset (halves)
#define OFF_VT  ((AQ_ROWS + 64) * AST)     // V tile offset (halves)
#define ATTN_SMEM ((AQ_ROWS + 128) * AST * 2)

__global__ __launch_bounds__(256)
void attn_f16(const __half* __restrict__ qkv, __half* __restrict__ out)
{
    extern __shared__ __half smh[];
    __half (*Qs)[AST] = (__half(*)[AST])smh;                 // Q, reused as P
    __half (*Ks)[AST] = (__half(*)[AST])(smh + OFF_KT);
    const uint32_t sbase = (uint32_t)__cvta_generic_to_shared(smh);
    const uint32_t sbK = sbase + OFF_KT * 2;
    const uint32_t sbV = sbase + OFF_VT * 2;

    const int bh   = blockIdx.y;
    const int b    = bh >> 3;
    const int h    = bh & 7;
    const int q0   = blockIdx.x * AQ_ROWS;
    const int tid  = threadIdx.x;
    const int lane = tid & 31;
    const int warp = tid >> 5;
    const int gid  = lane >> 2;
    const int tg   = lane & 3;
    const int wm   = warp * 16;              // 0..112

    const int sr = tid >> 3;                 // 0..31
    const int sc = (tid & 7) * 8;

    // ---- stage Q (128 rows) ----
    {
        const __half* gq = qkv + ((size_t)(b * Ls + q0 + sr)) * QS + h * HDs + sc;
        const uint32_t dq = sbase + (uint32_t)(sr * AST + sc) * 2;
#pragma unroll
        for (int i = 0; i < 4; i++)
            cp16(dq + i * (32 * AST * 2), gq + (size_t)32 * i * QS);
    }
    CP_COMMIT();
    CP_WAIT(0);
    __syncthreads();

    uint32_t qa[4][4];
#pragma unroll
    for (int kc = 0; kc < 4; kc++) {
        const __half* p0 = &Qs[wm + gid    ][kc * 16 + 2 * tg];
        const __half* p1 = &Qs[wm + gid + 8][kc * 16 + 2 * tg];
        qa[kc][0] = *(const uint32_t*)p0;
        qa[kc][1] = *(const uint32_t*)p1;
        qa[kc][2] = *(const uint32_t*)(p0 + 8);
        qa[kc][3] = *(const uint32_t*)(p1 + 8);
    }

    float o[8][4];
#pragma unroll
    for (int jn = 0; jn < 8; jn++)
#pragma unroll
        for (int c = 0; c < 4; c++) o[jn][c] = 0.f;
    float m0 = -1e30f, m1 = -1e30f, l0 = 0.f, l1 = 0.f;

    const int row0 = q0 + wm + gid;
    const int row1 = row0 + 8;
    const int kstart = max(0, q0 - WIN);
    const int kend   = min(Ls, q0 + AQ_ROWS + WIN);

    const int vkey = ((lane >> 3) & 1) * 8 + (lane & 7);
    const int vdim = ((lane >> 4) & 1) * 8;

    for (int kt = kstart; kt < kend; kt += 64) {
        __syncthreads();
        {
            const __half* gk = qkv + ((size_t)(b * Ls + kt + sr)) * QS + Ds     + h * HDs + sc;
            const __half* gv = qkv + ((size_t)(b * Ls + kt + sr)) * QS + 2 * Ds + h * HDs + sc;
            const uint32_t dk = sbK + (uint32_t)(sr * AST + sc) * 2;
            const uint32_t dv = sbV + (uint32_t)(sr * AST + sc) * 2;
#pragma unroll
            for (int i = 0; i < 2; i++) {
                cp16(dk + i * (32 * AST * 2), gk + (size_t)32 * i * QS);
                cp16(dv + i * (32 * AST * 2), gv + (size_t)32 * i * QS);
            }
        }
        CP_COMMIT();
        CP_WAIT(0);
        __syncthreads();

        // ---- S = Q K^T ----
        float s[8][4];
#pragma unroll
        for (int jn = 0; jn < 8; jn++)
#pragma unroll
            for (int c = 0; c < 4; c++) s[jn][c] = 0.f;

#pragma unroll
        for (int kc = 0; kc < 4; kc++) {
#pragma unroll
            for (int jn = 0; jn < 8; jn++) {
                const __half* bp = &Ks[jn * 8 + gid][kc * 16 + 2 * tg];
                uint32_t b0 = *(const uint32_t*)bp;
                uint32_t b1 = *(const uint32_t*)(bp + 8);
                mma_f16(s[jn], qa[kc][0], qa[kc][1], qa[kc][2], qa[kc][3], b0, b1);
            }
        }

        // ---- scale + band mask + row max ----
        float rmax0 = -1e30f, rmax1 = -1e30f;
#pragma unroll
        for (int jn = 0; jn < 8; jn++) {
            int cb = kt + jn * 8 + 2 * tg;
            s[jn][0] = (abs(cb     - row0) <= WIN) ? s[jn][0] * 0.125f : -1e30f;
            s[jn][1] = (abs(cb + 1 - row0) <= WIN) ? s[jn][1] * 0.125f : -1e30f;
            s[jn][2] = (abs(cb     - row1) <= WIN) ? s[jn][2] * 0.125f : -1e30f;
            s[jn][3] = (abs(cb + 1 - row1) <= WIN) ? s[jn][3] * 0.125f : -1e30f;
            rmax0 = fmaxf(rmax0, fmaxf(s[jn][0], s[jn][1]));
            rmax1 = fmaxf(rmax1, fmaxf(s[jn][2], s[jn][3]));
        }
        rmax0 = fmaxf(rmax0, __shfl_xor_sync(0xffffffffu, rmax0, 1));
        rmax0 = fmaxf(rmax0, __shfl_xor_sync(0xffffffffu, rmax0, 2));
        rmax1 = fmaxf(rmax1, __shfl_xor_sync(0xffffffffu, rmax1, 1));
        rmax1 = fmaxf(rmax1, __shfl_xor_sync(0xffffffffu, rmax1, 2));

        float mn0 = fmaxf(m0, rmax0);
        float mn1 = fmaxf(m1, rmax1);
        float sc0 = __expf(m0 - mn0);
        float sc1 = __expf(m1 - mn1);
        m0 = mn0; m1 = mn1;
        l0 *= sc0; l1 *= sc1;
#pragma unroll
        for (int jn = 0; jn < 8; jn++) {
            o[jn][0] *= sc0; o[jn][1] *= sc0;
            o[jn][2] *= sc1; o[jn][3] *= sc1;
        }

        // ---- P = exp(S - m) with masked-zero guard (tile may have no valid
        //      keys for a row when q-tile=128: exp(-1e30 - -1e30) trap) ----
#pragma unroll
        for (int jn = 0; jn < 8; jn++) {
            float p0 = (s[jn][0] > -1e29f) ? __expf(s[jn][0] - m0) : 0.f;
            float p1 = (s[jn][1] > -1e29f) ? __expf(s[jn][1] - m0) : 0.f;
            float p2 = (s[jn][2] > -1e29f) ? __expf(s[jn][2] - m1) : 0.f;
            float p3 = (s[jn][3] > -1e29f) ? __expf(s[jn][3] - m1) : 0.f;
            l0 += p0 + p1;
            l1 += p2 + p3;
            *(__half2*)&Qs[wm + gid    ][jn * 8 + 2 * tg] = __floats2half2_rn(p0, p1);
            *(__half2*)&Qs[wm + gid + 8][jn * 8 + 2 * tg] = __floats2half2_rn(p2, p3);
        }
        __syncwarp();   // warp reads only its own 16 P rows

        // ---- O += P V ----
#pragma unroll
        for (int kc = 0; kc < 4; kc++) {
            const __half* pp0 = &Qs[wm + gid    ][kc * 16 + 2 * tg];
            const __half* pp1 = &Qs[wm + gid + 8][kc * 16 + 2 * tg];
            uint32_t a0 = *(const uint32_t*)pp0;
            uint32_t a1 = *(const uint32_t*)pp1;
            uint32_t a2 = *(const uint32_t*)(pp0 + 8);
            uint32_t a3 = *(const uint32_t*)(pp1 + 8);
#pragma unroll
            for (int jp = 0; jp < 4; jp++) {
                uint32_t vaddr = sbV + (uint32_t)((kc * 16 + vkey) * AST + jp * 16 + vdim) * 2;
                uint32_t b0, b1, b2, b3;
                ldsm_x4_trans(b0, b1, b2, b3, vaddr);
                mma_f16(o[jp * 2    ], a0, a1, a2, a3, b0, b1);
                mma_f16(o[jp * 2 + 1], a0, a1, a2, a3, b2, b3);
            }
        }
    }

    l0 += __shfl_xor_sync(0xffffffffu, l0, 1);
    l0 += __shfl_xor_sync(0xffffffffu, l0, 2);
    l1 += __shfl_xor_sync(0xffffffffu, l1, 1);
    l1 += __shfl_xor_sync(0xffffffffu, l1, 2);
    const float inv0 = 1.f / l0;
    const float inv1 = 1.f / l1;

    __half* o0 = out + ((size_t)(b * Ls + row0)) * Ds + h * HDs;
    __half* o1 = out + ((size_t)(b * Ls + row1)) * Ds + h * HDs;
#pragma unroll
    for (int jn = 0; jn < 8; jn++) {
        int c = jn * 8 + 2 * tg;
        *(__half2*)&o0[c] = __floats2half2_rn(o[jn][0] * inv0, o[jn][1] * inv0);
        *(__half2*)&o1[c] = __floats2half2_rn(o[jn][2] * inv1, o[jn][3] * inv1);
    }
}

// ---------------- residual + LayerNorm (round-10 version) -------------------
__global__ __launch_bounds__(128)
void add_ln(const float* __restrict__ x, const float* __restrict__ r,
            const float* __restrict__ g, const float* __restrict__ bta,
            float* __restrict__ out, __half* __restrict__ out_r)
{
    const int row = blockIdx.x;
    const int tid = threadIdx.x;
    const float* xr = x + (size_t)row * Ds;
    const float* rr = r + (size_t)row * Ds;

    __shared__ float t[Ds];
    __shared__ float s1[4], s2[4];

    float s = 0.f, ss = 0.f;
#pragma unroll
    for (int i = 0; i < 4; i++) {
        int c = tid + i * 128;
        float u = xr[c] + rr[c];
        t[c] = u;
        s += u;
        ss = fmaf(u, u, ss);
    }
#pragma unroll
    for (int o = 16; o; o >>= 1) {
        s  += __shfl_xor_sync(0xffffffffu, s,  o);
        ss += __shfl_xor_sync(0xffffffffu, ss, o);
    }
    if ((tid & 31) == 0) { s1[tid >> 5] = s; s2[tid >> 5] = ss; }
    __syncthreads();
    float S  = s1[0] + s1[1] + s1[2] + s1[3];
    float SS = s2[0] + s2[1] + s2[2] + s2[3];
    float mu   = S * (1.f / Ds);
    float var  = SS * (1.f / Ds) - mu * mu;
    float rstd = rsqrtf(var + 1e-5f);
#pragma unroll
    for (int i = 0; i < 4; i++) {
        int c = tid + i * 128;
        float val = (t[c] - mu) * rstd * g[c] + bta[c];
        out[(size_t)row * Ds + c] = val;
        if (out_r) out_r[(size_t)row * Ds + c] = __float2half(val);
    }
}

// ---------------- launch ----------------------------------------------------
extern "C" void kernel_launch(void* const* d_in, const int* in_sizes, int n_in,
                              void* d_out, int out_size)
{
    const float* x    = (const float*)d_in[0];
    const float* Wq   = (const float*)d_in[1];
    const float* bq   = (const float*)d_in[2];
    const float* Wk   = (const float*)d_in[3];
    const float* bk   = (const float*)d_in[4];
    const float* Wv   = (const float*)d_in[5];
    const float* bv   = (const float*)d_in[6];
    const float* Wo   = (const float*)d_in[7];
    const float* bo   = (const float*)d_in[8];
    const float* ln1g = (const float*)d_in[9];
    const float* ln1b = (const float*)d_in[10];
    const float* W1   = (const float*)d_in[11];
    const float* b1   = (const float*)d_in[12];
    const float* W2   = (const float*)d_in[13];
    const float* b2   = (const float*)d_in[14];
    const float* ln2g = (const float*)d_in[15];
    const float* ln2b = (const float*)d_in[16];
    float* out = (float*)d_out;

    __half *xh, *qkv, *att, *hr, *ff1, *wqkvt, *wot, *w1t, *w2t;
    float  *prj, *h, *ff2, *bqkv;
    cudaGetSymbolAddress((void**)&xh,    g_xh);
    cudaGetSymbolAddress((void**)&qkv,   g_qkv);
    cudaGetSymbolAddress((void**)&att,   g_att);
    cudaGetSymbolAddress((void**)&prj,   g_prj);
    cudaGetSymbolAddress((void**)&h,     g_h);
    cudaGetSymbolAddress((void**)&hr,    g_hr);
    cudaGetSymbolAddress((void**)&ff1,   g_ff1);
    cudaGetSymbolAddress((void**)&ff2,   g_ff2);
    cudaGetSymbolAddress((void**)&wqkvt, g_wqkvt);
    cudaGetSymbolAddress((void**)&wot,   g_wot);
    cudaGetSymbolAddress((void**)&w1t,   g_w1t);
    cudaGetSymbolAddress((void**)&w2t,   g_w2t);
    cudaGetSymbolAddress((void**)&bqkv,  g_bqkv);

    cudaFuncSetAttribute(hgemm,    cudaFuncAttributeMaxDynamicSharedMemorySize, HG_SMEM);
    cudaFuncSetAttribute(attn_f16, cudaFuncAttributeMaxDynamicSharedMemorySize, ATTN_SMEM);

    // prologue
    to_half<<<(Ms * Ds / 4 + 255) / 256, 256>>>(x, xh, Ms * Ds / 4);
    transpose_all<<<3072, dim3(32, 8)>>>(Wq, Wk, Wv, Wo, W1, W2, wqkvt, wot, w1t, w2t);
    concat3<<<3, 512>>>(bq, bk, bv, bqkv);

    // fused QKV -> half
    hgemm<<<dim3(QS / 256, Ms / 128), 256, HG_SMEM>>>(xh, wqkvt, bqkv, qkv,
                                                      Ms, QS, Ds, 0, 2);

    attn_f16<<<dim3(Ls / AQ_ROWS, Bb * Hh), 256, ATTN_SMEM>>>(qkv, att);

    hgemm<<<dim3(Ds / 256, Ms / 128), 256, HG_SMEM>>>(att, wot, bo, prj,
                                                      Ms, Ds, Ds, 0, 0);
    add_ln<<<Ms, 128>>>(x, prj, ln1g, ln1b, h, hr);

    hgemm<<<dim3(FFs / 256, Ms / 128), 256, HG_SMEM>>>(hr, w1t, b1, ff1,
                                                       Ms, FFs, Ds, 1, 2);
    hgemm<<<dim3(Ds / 256, Ms / 128), 256, HG_SMEM>>>(ff1, w2t, b2, ff2,
                                                      Ms, Ds, FFs, 0, 0);
    add_ln<<<Ms, 128>>>(h, ff2, ln2g, ln2b, out, nullptr);
}

// round 15
// speedup vs baseline: 1.0564x; 1.0564x over previous
#include <cuda_runtime.h>
#include <cuda_fp16.h>
#include <cstdint>

#define Bb  2
#define Ls  4096
#define Ds  512
#define Hh  8
#define HDs 64
#define FFs 2048
#define WIN 128
#define Ms  (Bb*Ls)
#define QS  1536     // fused qkv row stride (q|k|v) in halves

// ---------------- scratch (device globals: allocation-guard safe) ----------
__device__ __half g_xh  [Ms*Ds];
__device__ __half g_qkv [Ms*QS];
__device__ __half g_att [Ms*Ds];
__device__ float  g_prj [Ms*Ds];
__device__ float  g_h   [Ms*Ds];
__device__ __half g_hr  [Ms*Ds];
__device__ __half g_ff1 [Ms*FFs];
__device__ float  g_ff2 [Ms*Ds];
__device__ __half g_wqkvt[3*Ds*Ds];
__device__ __half g_wot [Ds*Ds];
__device__ __half g_w1t [Ds*FFs];
__device__ __half g_w2t [FFs*Ds];
__device__ float  g_bqkv[QS];

// ---------------- helpers ---------------------------------------------------
__device__ __forceinline__ void cp16(uint32_t dst_smem, const void* src) {
    asm volatile("cp.async.ca.shared.global [%0], [%1], 16;\n"
                 :: "r"(dst_smem), "l"(src));
}
#define CP_COMMIT() asm volatile("cp.async.commit_group;\n")
#define CP_WAIT(n)  asm volatile("cp.async.wait_group %0;\n" :: "n"(n))

__device__ __forceinline__ uint32_t f2tf(float x) {
    uint32_t u;
    asm("cvt.rna.tf32.f32 %0, %1;" : "=r"(u) : "f"(x));
    return u;
}
__device__ __forceinline__ float rna(float x) { return __uint_as_float(f2tf(x)); }

__device__ __forceinline__ void mma_f16(float d[4],
    uint32_t a0, uint32_t a1, uint32_t a2, uint32_t a3, uint32_t b0, uint32_t b1)
{
    asm volatile(
        "mma.sync.aligned.m16n8k16.row.col.f32.f16.f16.f32 "
        "{%0,%1,%2,%3}, {%4,%5,%6,%7}, {%8,%9}, {%0,%1,%2,%3};\n"
        : "+f"(d[0]), "+f"(d[1]), "+f"(d[2]), "+f"(d[3])
        : "r"(a0), "r"(a1), "r"(a2), "r"(a3), "r"(b0), "r"(b1));
}

__device__ __forceinline__ void ldsm_x4(uint32_t r[4], uint32_t addr)
{
    asm volatile("ldmatrix.sync.aligned.m8n8.x4.shared.b16 {%0,%1,%2,%3}, [%4];"
                 : "=r"(r[0]), "=r"(r[1]), "=r"(r[2]), "=r"(r[3]) : "r"(addr));
}
__device__ __forceinline__ void ldsm_x4_trans(uint32_t& r0, uint32_t& r1,
                                              uint32_t& r2, uint32_t& r3, uint32_t addr)
{
    asm volatile("ldmatrix.sync.aligned.m8n8.x4.trans.shared.b16 {%0,%1,%2,%3}, [%4];"
                 : "=r"(r0), "=r"(r1), "=r"(r2), "=r"(r3) : "r"(addr));
}

// ================= fused prologue ===========================================
// blocks [0,3072): weight transpose tiles (W[K][N] f32 -> Wt[N][K] half)
// blocks [3072,4096): x -> half conversion (1024 float4 per block)
// block  4096: bias concat (q|k|v)
__global__ __launch_bounds__(256)
void prologue_all(const float* __restrict__ x,
                  const float* __restrict__ Wq, const float* __restrict__ Wk,
                  const float* __restrict__ Wv, const float* __restrict__ Wo,
                  const float* __restrict__ W1, const float* __restrict__ W2,
                  const float* __restrict__ bq, const float* __restrict__ bk,
                  const float* __restrict__ bv,
                  __half* __restrict__ xh,
                  __half* __restrict__ wqkvt, __half* __restrict__ wot,
                  __half* __restrict__ w1t,   __half* __restrict__ w2t,
                  float* __restrict__ bqkv)
{
    const int bid = blockIdx.x;
    const int tid = threadIdx.x;

    if (bid < 3072) {
        const float* W; __half* Wt; int K, N, tile;
        if      (bid < 256)  { W = Wq; Wt = wqkvt;               K = Ds;  N = Ds;  tile = bid; }
        else if (bid < 512)  { W = Wk; Wt = wqkvt + Ds * Ds;     K = Ds;  N = Ds;  tile = bid - 256; }
        else if (bid < 768)  { W = Wv; Wt = wqkvt + 2 * Ds * Ds; K = Ds;  N = Ds;  tile = bid - 512; }
        else if (bid < 1024) { W = Wo; Wt = wot;                 K = Ds;  N = Ds;  tile = bid - 768; }
        else if (bid < 2048) { W = W1; Wt = w1t;                 K = Ds;  N = FFs; tile = bid - 1024; }
        else                 { W = W2; Wt = w2t;                 K = FFs; N = Ds;  tile = bid - 2048; }
        const int ntx = N / 32;
        const int nx = (tile % ntx) * 32, ky = (tile / ntx) * 32;

        __shared__ float t[32][33];
        const int xx = tid & 31, yy = tid >> 5;   // 32 x 8
#pragma unroll
        for (int j = 0; j < 32; j += 8)
            t[yy + j][xx] = W[(size_t)(ky + yy + j) * N + nx + xx];
        __syncthreads();
#pragma unroll
        for (int j = 0; j < 32; j += 8)
            Wt[(size_t)(nx + yy + j) * K + ky + xx] = __float2half(t[xx][yy + j]);
    } else if (bid < 4096) {
        // x -> half: 1,048,576 float4 total / 1024 blocks = 1024 per block
        const int base = (bid - 3072) * 1024;
#pragma unroll
        for (int it = 0; it < 4; it++) {
            int i = base + tid + it * 256;
            float4 v = ((const float4*)x)[i];
            __half2 lo = __floats2half2_rn(v.x, v.y);
            __half2 hi = __floats2half2_rn(v.z, v.w);
            ((uint2*)xh)[i] = make_uint2(*(uint32_t*)&lo, *(uint32_t*)&hi);
        }
    } else {
        for (int i = tid; i < QS; i += 256)
            bqkv[i] = (i < Ds) ? bq[i] : (i < 2 * Ds) ? bk[i - Ds] : bv[i - 2 * Ds];
    }
}

// ================= fp16 tensor-core GEMM (round-10 best) ====================
// C[M,N] = A[M,K] @ Bt[N,K]^T + bias.
// 256 thr, CTA tile 128x256x64, warp grid 2x4, warp tile 64x64.
// 3-stage cp.async pipeline, ldmatrix fragment loads.
// out_mode: 0 = fp32, 1 = fp32 rna-rounded, 2 = half
#define HST    72
#define HAS    (128 * HST)
#define HBS    (256 * HST)
#define HSTG   (HAS + HBS)
#define HG_SMEM (3 * HSTG * 2)

__global__ __launch_bounds__(256, 1)
void hgemm(const __half* __restrict__ A, const __half* __restrict__ Bt,
           const float* __restrict__ bias, void* __restrict__ Cv,
           int M, int N, int K, int relu, int out_mode)
{
    extern __shared__ __align__(256) __half sh[];
    const uint32_t sb = (uint32_t)__cvta_generic_to_shared(sh);

    const int tid  = threadIdx.x;
    const int lane = tid & 31;
    const int warp = tid >> 5;
    const int gid  = lane >> 2;
    const int tg   = lane & 3;
    const int wm   = (warp >> 2) * 64;
    const int wn   = (warp & 3) * 64;
    const int bm   = blockIdx.y * 128;
    const int bn   = blockIdx.x * 256;

    const int ar = tid >> 3;
    const int ac = (tid & 7) * 8;

    const int a_row = wm + ((lane >> 3) & 1) * 8 + (lane & 7);
    const int a_k   = ((lane >> 4) & 1) * 8;
    const int b_row = wn + ((lane >> 4) & 1) * 8 + (lane & 7);
    const int b_k   = ((lane >> 3) & 1) * 8;

    float d[4][8][4];
#pragma unroll
    for (int i = 0; i < 4; i++)
#pragma unroll
        for (int j = 0; j < 8; j++)
#pragma unroll
            for (int c = 0; c < 4; c++) d[i][j][c] = 0.f;

    auto do_load = [&](int stage, int k0) {
        const __half* pa = A  + (size_t)(bm + ar) * K + k0 + ac;
        const __half* pb = Bt + (size_t)(bn + ar) * K + k0 + ac;
        const uint32_t ba = sb + (uint32_t)stage * (HSTG * 2);
        const uint32_t bb = ba + HAS * 2;
#pragma unroll
        for (int i = 0; i < 4; i++) {
            uint32_t off = (uint32_t)((ar + 32 * i) * HST + ac) * 2;
            cp16(ba + off, pa + (size_t)32 * i * K);
        }
#pragma unroll
        for (int i = 0; i < 8; i++) {
            uint32_t off = (uint32_t)((ar + 32 * i) * HST + ac) * 2;
            cp16(bb + off, pb + (size_t)32 * i * K);
        }
    };

    const int T = K / 64;
    do_load(0, 0);
    CP_COMMIT();
    if (T > 1) { do_load(1, 64); CP_COMMIT(); }

    for (int t = 0; t < T; t++) {
        if (t + 1 < T) { CP_WAIT(1); } else { CP_WAIT(0); }
        __syncthreads();

        const int buf = t % 3;
        const uint32_t sA = sb + (uint32_t)buf * (HSTG * 2);
        const uint32_t sB = sA + HAS * 2;

#pragma unroll
        for (int kc = 0; kc < 4; kc++) {
            const int kk = kc * 16;
            uint32_t af[4][4], bf[4][4];
#pragma unroll
            for (int im = 0; im < 4; im++)
                ldsm_x4(af[im], sA + (uint32_t)((a_row + im * 16) * HST + kk + a_k) * 2);
#pragma unroll
            for (int jp = 0; jp < 4; jp++)
                ldsm_x4(bf[jp], sB + (uint32_t)((b_row + jp * 16) * HST + kk + b_k) * 2);
#pragma unroll
            for (int im = 0; im < 4; im++)
#pragma unroll
                for (int jn = 0; jn < 8; jn++)
                    mma_f16(d[im][jn], af[im][0], af[im][1], af[im][2], af[im][3],
                            bf[jn >> 1][(jn & 1) * 2], bf[jn >> 1][(jn & 1) * 2 + 1]);
        }

        if (t + 2 < T) { do_load((t + 2) % 3, (t + 2) * 64); CP_COMMIT(); }
    }

    // epilogue
#pragma unroll
    for (int jn = 0; jn < 8; jn++) {
        const int col = bn + wn + jn * 8 + 2 * tg;
        float2 bv = *(const float2*)&bias[col];
#pragma unroll
        for (int im = 0; im < 4; im++) {
            const int row = bm + wm + im * 16 + gid;
            float v0 = d[im][jn][0] + bv.x, v1 = d[im][jn][1] + bv.y;
            float v2 = d[im][jn][2] + bv.x, v3 = d[im][jn][3] + bv.y;
            if (relu) {
                v0 = fmaxf(v0, 0.f); v1 = fmaxf(v1, 0.f);
                v2 = fmaxf(v2, 0.f); v3 = fmaxf(v3, 0.f);
            }
            if (out_mode == 2) {
                __half* Ch = (__half*)Cv;
                *(__half2*)&Ch[(size_t)row       * N + col] = __floats2half2_rn(v0, v1);
                *(__half2*)&Ch[(size_t)(row + 8) * N + col] = __floats2half2_rn(v2, v3);
            } else {
                if (out_mode == 1) { v0 = rna(v0); v1 = rna(v1); v2 = rna(v2); v3 = rna(v3); }
                float* Cf = (float*)Cv;
                *(float2*)&Cf[(size_t)row       * N + col] = make_float2(v0, v1);
                *(float2*)&Cf[(size_t)(row + 8) * N + col] = make_float2(v2, v3);
            }
        }
    }
}

// ============== banded attention, full fp16 m16n8k16 (round-10 best) ========
#define AST 72
#define ATTN_SMEM (3 * 64 * AST * 2)

__global__ __launch_bounds__(128)
void attn_f16(const __half* __restrict__ qkv, __half* __restrict__ out)
{
    extern __shared__ __half smh[];
    __half (*Qs)[AST] = (__half(*)[AST])smh;                 // also Ps
    __half (*Ks)[AST] = (__half(*)[AST])(smh + 64 * AST);
    const uint32_t sbase = (uint32_t)__cvta_generic_to_shared(smh);
    const uint32_t sbK = sbase + 64 * AST * 2;
    const uint32_t sbV = sbase + 2 * 64 * AST * 2;

    const int bh   = blockIdx.y;
    const int b    = bh >> 3;
    const int h    = bh & 7;
    const int q0   = blockIdx.x * 64;
    const int tid  = threadIdx.x;
    const int lane = tid & 31;
    const int warp = tid >> 5;
    const int gid  = lane >> 2;
    const int tg   = lane & 3;
    const int wm   = warp * 16;

    const int sr = tid >> 3;
    const int sc = (tid & 7) * 8;

    {
        const __half* gq = qkv + ((size_t)(b * Ls + q0 + sr)) * QS + h * HDs + sc;
        const uint32_t dq = sbase + (uint32_t)(sr * AST + sc) * 2;
#pragma unroll
        for (int i = 0; i < 4; i++)
            cp16(dq + i * (16 * AST * 2), gq + (size_t)16 * i * QS);
    }
    CP_COMMIT();
    CP_WAIT(0);
    __syncthreads();

    uint32_t qa[4][4];
#pragma unroll
    for (int kc = 0; kc < 4; kc++) {
        const __half* p0 = &Qs[wm + gid    ][kc * 16 + 2 * tg];
        const __half* p1 = &Qs[wm + gid + 8][kc * 16 + 2 * tg];
        qa[kc][0] = *(const uint32_t*)p0;
        qa[kc][1] = *(const uint32_t*)p1;
        qa[kc][2] = *(const uint32_t*)(p0 + 8);
        qa[kc][3] = *(const uint32_t*)(p1 + 8);
    }

    float o[8][4];
#pragma unroll
    for (int jn = 0; jn < 8; jn++)
#pragma unroll
        for (int c = 0; c < 4; c++) o[jn][c] = 0.f;
    float m0 = -1e30f, m1 = -1e30f, l0 = 0.f, l1 = 0.f;

    const int row0 = q0 + wm + gid;
    const int row1 = row0 + 8;
    const int kstart = max(0, q0 - WIN);
    const int kend   = min(Ls, q0 + 64 + WIN);

    const int vkey = ((lane >> 3) & 1) * 8 + (lane & 7);
    const int vdim = ((lane >> 4) & 1) * 8;

    for (int kt = kstart; kt < kend; kt += 64) {
        __syncthreads();
        {
            const __half* gk = qkv + ((size_t)(b * Ls + kt + sr)) * QS + Ds     + h * HDs + sc;
            const __half* gv = qkv + ((size_t)(b * Ls + kt + sr)) * QS + 2 * Ds + h * HDs + sc;
            const uint32_t dk = sbK + (uint32_t)(sr * AST + sc) * 2;
            const uint32_t dv = sbV + (uint32_t)(sr * AST + sc) * 2;
#pragma unroll
            for (int i = 0; i < 4; i++) {
                cp16(dk + i * (16 * AST * 2), gk + (size_t)16 * i * QS);
                cp16(dv + i * (16 * AST * 2), gv + (size_t)16 * i * QS);
            }
        }
        CP_COMMIT();
        CP_WAIT(0);
        __syncthreads();

        float s[8][4];
#pragma unroll
        for (int jn = 0; jn < 8; jn++)
#pragma unroll
            for (int c = 0; c < 4; c++) s[jn][c] = 0.f;

#pragma unroll
        for (int kc = 0; kc < 4; kc++) {
#pragma unroll
            for (int jn = 0; jn < 8; jn++) {
                const __half* bp = &Ks[jn * 8 + gid][kc * 16 + 2 * tg];
                uint32_t b0 = *(const uint32_t*)bp;
                uint32_t b1 = *(const uint32_t*)(bp + 8);
                mma_f16(s[jn], qa[kc][0], qa[kc][1], qa[kc][2], qa[kc][3], b0, b1);
            }
        }

        float rmax0 = -1e30f, rmax1 = -1e30f;
#pragma unroll
        for (int jn = 0; jn < 8; jn++) {
            int cb = kt + jn * 8 + 2 * tg;
            s[jn][0] = (abs(cb     - row0) <= WIN) ? s[jn][0] * 0.125f : -1e30f;
            s[jn][1] = (abs(cb + 1 - row0) <= WIN) ? s[jn][1] * 0.125f : -1e30f;
            s[jn][2] = (abs(cb     - row1) <= WIN) ? s[jn][2] * 0.125f : -1e30f;
            s[jn][3] = (abs(cb + 1 - row1) <= WIN) ? s[jn][3] * 0.125f : -1e30f;
            rmax0 = fmaxf(rmax0, fmaxf(s[jn][0], s[jn][1]));
            rmax1 = fmaxf(rmax1, fmaxf(s[jn][2], s[jn][3]));
        }
        rmax0 = fmaxf(rmax0, __shfl_xor_sync(0xffffffffu, rmax0, 1));
        rmax0 = fmaxf(rmax0, __shfl_xor_sync(0xffffffffu, rmax0, 2));
        rmax1 = fmaxf(rmax1, __shfl_xor_sync(0xffffffffu, rmax1, 1));
        rmax1 = fmaxf(rmax1, __shfl_xor_sync(0xffffffffu, rmax1, 2));

        float mn0 = fmaxf(m0, rmax0);
        float mn1 = fmaxf(m1, rmax1);
        float sc0 = __expf(m0 - mn0);
        float sc1 = __expf(m1 - mn1);
        m0 = mn0; m1 = mn1;
        l0 *= sc0; l1 *= sc1;
#pragma unroll
        for (int jn = 0; jn < 8; jn++) {
            o[jn][0] *= sc0; o[jn][1] *= sc0;
            o[jn][2] *= sc1; o[jn][3] *= sc1;
        }

#pragma unroll
        for (int jn = 0; jn < 8; jn++) {
            float p0 = __expf(s[jn][0] - m0);
            float p1 = __expf(s[jn][1] - m0);
            float p2 = __expf(s[jn][2] - m1);
            float p3 = __expf(s[jn][3] - m1);
            l0 += p0 + p1;
            l1 += p2 + p3;
            *(__half2*)&Qs[wm + gid    ][jn * 8 + 2 * tg] = __floats2half2_rn(p0, p1);
            *(__half2*)&Qs[wm + gid + 8][jn * 8 + 2 * tg] = __floats2half2_rn(p2, p3);
        }
        __syncwarp();

#pragma unroll
        for (int kc = 0; kc < 4; kc++) {
            const __half* pp0 = &Qs[wm + gid    ][kc * 16 + 2 * tg];
            const __half* pp1 = &Qs[wm + gid + 8][kc * 16 + 2 * tg];
            uint32_t a0 = *(const uint32_t*)pp0;
            uint32_t a1 = *(const uint32_t*)pp1;
            uint32_t a2 = *(const uint32_t*)(pp0 + 8);
            uint32_t a3 = *(const uint32_t*)(pp1 + 8);
#pragma unroll
            for (int jp = 0; jp < 4; jp++) {
                uint32_t vaddr = sbV + (uint32_t)((kc * 16 + vkey) * AST + jp * 16 + vdim) * 2;
                uint32_t b0, b1, b2, b3;
                ldsm_x4_trans(b0, b1, b2, b3, vaddr);
                mma_f16(o[jp * 2    ], a0, a1, a2, a3, b0, b1);
                mma_f16(o[jp * 2 + 1], a0, a1, a2, a3, b2, b3);
            }
        }
    }

    l0 += __shfl_xor_sync(0xffffffffu, l0, 1);
    l0 += __shfl_xor_sync(0xffffffffu, l0, 2);
    l1 += __shfl_xor_sync(0xffffffffu, l1, 1);
    l1 += __shfl_xor_sync(0xffffffffu, l1, 2);
    const float inv0 = 1.f / l0;
    const float inv1 = 1.f / l1;

    __half* o0 = out + ((size_t)(b * Ls + row0)) * Ds + h * HDs;
    __half* o1 = out + ((size_t)(b * Ls + row1)) * Ds + h * HDs;
#pragma unroll
    for (int jn = 0; jn < 8; jn++) {
        int c = jn * 8 + 2 * tg;
        *(__half2*)&o0[c] = __floats2half2_rn(o[jn][0] * inv0, o[jn][1] * inv0);
        *(__half2*)&o1[c] = __floats2half2_rn(o[jn][2] * inv1, o[jn][3] * inv1);
    }
}

// ---------------- residual + LayerNorm (round-10 version) -------------------
__global__ __launch_bounds__(128)
void add_ln(const float* __restrict__ x, const float* __restrict__ r,
            const float* __restrict__ g, const float* __restrict__ bta,
            float* __restrict__ out, __half* __restrict__ out_r)
{
    const int row = blockIdx.x;
    const int tid = threadIdx.x;
    const float* xr = x + (size_t)row * Ds;
    const float* rr = r + (size_t)row * Ds;

    __shared__ float t[Ds];
    __shared__ float s1[4], s2[4];

    float s = 0.f, ss = 0.f;
#pragma unroll
    for (int i = 0; i < 4; i++) {
        int c = tid + i * 128;
        float u = xr[c] + rr[c];
        t[c] = u;
        s += u;
        ss = fmaf(u, u, ss);
    }
#pragma unroll
    for (int o = 16; o; o >>= 1) {
        s  += __shfl_xor_sync(0xffffffffu, s,  o);
        ss += __shfl_xor_sync(0xffffffffu, ss, o);
    }
    if ((tid & 31) == 0) { s1[tid >> 5] = s; s2[tid >> 5] = ss; }
    __syncthreads();
    float S  = s1[0] + s1[1] + s1[2] + s1[3];
    float SS = s2[0] + s2[1] + s2[2] + s2[3];
    float mu   = S * (1.f / Ds);
    float var  = SS * (1.f / Ds) - mu * mu;
    float rstd = rsqrtf(var + 1e-5f);
#pragma unroll
    for (int i = 0; i < 4; i++) {
        int c = tid + i * 128;
        float val = (t[c] - mu) * rstd * g[c] + bta[c];
        out[(size_t)row * Ds + c] = val;
        if (out_r) out_r[(size_t)row * Ds + c] = __float2half(val);
    }
}

// ---------------- launch ----------------------------------------------------
extern "C" void kernel_launch(void* const* d_in, const int* in_sizes, int n_in,
                              void* d_out, int out_size)
{
    const float* x    = (const float*)d_in[0];
    const float* Wq   = (const float*)d_in[1];
    const float* bq   = (const float*)d_in[2];
    const float* Wk   = (const float*)d_in[3];
    const float* bk   = (const float*)d_in[4];
    const float* Wv   = (const float*)d_in[5];
    const float* bv   = (const float*)d_in[6];
    const float* Wo   = (const float*)d_in[7];
    const float* bo   = (const float*)d_in[8];
    const float* ln1g = (const float*)d_in[9];
    const float* ln1b = (const float*)d_in[10];
    const float* W1   = (const float*)d_in[11];
    const float* b1   = (const float*)d_in[12];
    const float* W2   = (const float*)d_in[13];
    const float* b2   = (const float*)d_in[14];
    const float* ln2g = (const float*)d_in[15];
    const float* ln2b = (const float*)d_in[16];
    float* out = (float*)d_out;

    __half *xh, *qkv, *att, *hr, *ff1, *wqkvt, *wot, *w1t, *w2t;
    float  *prj, *h, *ff2, *bqkv;
    cudaGetSymbolAddress((void**)&xh,    g_xh);
    cudaGetSymbolAddress((void**)&qkv,   g_qkv);
    cudaGetSymbolAddress((void**)&att,   g_att);
    cudaGetSymbolAddress((void**)&prj,   g_prj);
    cudaGetSymbolAddress((void**)&h,     g_h);
    cudaGetSymbolAddress((void**)&hr,    g_hr);
    cudaGetSymbolAddress((void**)&ff1,   g_ff1);
    cudaGetSymbolAddress((void**)&ff2,   g_ff2);
    cudaGetSymbolAddress((void**)&wqkvt, g_wqkvt);
    cudaGetSymbolAddress((void**)&wot,   g_wot);
    cudaGetSymbolAddress((void**)&w1t,   g_w1t);
    cudaGetSymbolAddress((void**)&w2t,   g_w2t);
    cudaGetSymbolAddress((void**)&bqkv,  g_bqkv);

    cudaFuncSetAttribute(hgemm,    cudaFuncAttributeMaxDynamicSharedMemorySize, HG_SMEM);
    cudaFuncSetAttribute(attn_f16, cudaFuncAttributeMaxDynamicSharedMemorySize, ATTN_SMEM);

    // fused prologue: weight transposes + x->half + bias concat, one launch
    prologue_all<<<4097, 256>>>(x, Wq, Wk, Wv, Wo, W1, W2, bq, bk, bv,
                                xh, wqkvt, wot, w1t, w2t, bqkv);

    // fused QKV -> half
    hgemm<<<dim3(QS / 256, Ms / 128), 256, HG_SMEM>>>(xh, wqkvt, bqkv, qkv,
                                                      Ms, QS, Ds, 0, 2);

    attn_f16<<<dim3(Ls / 64, Bb * Hh), 128, ATTN_SMEM>>>(qkv, att);

    hgemm<<<dim3(Ds / 256, Ms / 128), 256, HG_SMEM>>>(att, wot, bo, prj,
                                                      Ms, Ds, Ds, 0, 0);
    add_ln<<<Ms, 128>>>(x, prj, ln1g, ln1b, h, hr);

    hgemm<<<dim3(FFs / 256, Ms / 128), 256, HG_SMEM>>>(hr, w1t, b1, ff1,
                                                       Ms, FFs, Ds, 1, 2);
    hgemm<<<dim3(Ds / 256, Ms / 128), 256, HG_SMEM>>>(ff1, w2t, b2, ff2,
                                                      Ms, Ds, FFs, 0, 0);
    add_ln<<<Ms, 128>>>(h, ff2, ln2g, ln2b, out, nullptr);
}

// round 16
// speedup vs baseline: 1.0726x; 1.0154x over previous
#include <cuda_runtime.h>
#include <cuda_fp16.h>
#include <cstdint>

#define Bb  2
#define Ls  4096
#define Ds  512
#define Hh  8
#define HDs 64
#define FFs 2048
#define WIN 128
#define Ms  (Bb*Ls)
#define QS  1536     // fused qkv row stride (q|k|v) in halves

// ---------------- scratch (device globals: allocation-guard safe) ----------
__device__ __half g_xh  [Ms*Ds];
__device__ __half g_qkv [Ms*QS];
__device__ __half g_att [Ms*Ds];
__device__ float  g_prj [Ms*Ds];
__device__ float  g_h   [Ms*Ds];
__device__ __half g_hr  [Ms*Ds];
__device__ __half g_ff1 [Ms*FFs];
__device__ float  g_ff2 [Ms*Ds];
__device__ __half g_wqkvt[3*Ds*Ds];
__device__ __half g_wot [Ds*Ds];
__device__ __half g_w1t [Ds*FFs];
__device__ __half g_w2t [FFs*Ds];
__device__ float  g_bqkv[QS];

// ---------------- helpers ---------------------------------------------------
__device__ __forceinline__ void cp16(uint32_t dst_smem, const void* src) {
    asm volatile("cp.async.ca.shared.global [%0], [%1], 16;\n"
                 :: "r"(dst_smem), "l"(src));
}
#define CP_COMMIT() asm volatile("cp.async.commit_group;\n")
#define CP_WAIT(n)  asm volatile("cp.async.wait_group %0;\n" :: "n"(n))

__device__ __forceinline__ uint32_t f2tf(float x) {
    uint32_t u;
    asm("cvt.rna.tf32.f32 %0, %1;" : "=r"(u) : "f"(x));
    return u;
}
__device__ __forceinline__ float rna(float x) { return __uint_as_float(f2tf(x)); }

__device__ __forceinline__ void mma_f16(float d[4],
    uint32_t a0, uint32_t a1, uint32_t a2, uint32_t a3, uint32_t b0, uint32_t b1)
{
    asm volatile(
        "mma.sync.aligned.m16n8k16.row.col.f32.f16.f16.f32 "
        "{%0,%1,%2,%3}, {%4,%5,%6,%7}, {%8,%9}, {%0,%1,%2,%3};\n"
        : "+f"(d[0]), "+f"(d[1]), "+f"(d[2]), "+f"(d[3])
        : "r"(a0), "r"(a1), "r"(a2), "r"(a3), "r"(b0), "r"(b1));
}

__device__ __forceinline__ void ldsm_x4(uint32_t r[4], uint32_t addr)
{
    asm volatile("ldmatrix.sync.aligned.m8n8.x4.shared.b16 {%0,%1,%2,%3}, [%4];"
                 : "=r"(r[0]), "=r"(r[1]), "=r"(r[2]), "=r"(r[3]) : "r"(addr));
}
__device__ __forceinline__ void ldsm_x4_trans(uint32_t& r0, uint32_t& r1,
                                              uint32_t& r2, uint32_t& r3, uint32_t addr)
{
    asm volatile("ldmatrix.sync.aligned.m8n8.x4.trans.shared.b16 {%0,%1,%2,%3}, [%4];"
                 : "=r"(r0), "=r"(r1), "=r"(r2), "=r"(r3) : "r"(addr));
}

// ================= fused prologue ===========================================
// blocks [0,3072): weight transpose tiles (W[K][N] f32 -> Wt[N][K] half)
// blocks [3072,4096): x -> half conversion (1024 float4 per block)
// block  4096: bias concat (q|k|v)
__global__ __launch_bounds__(256)
void prologue_all(const float* __restrict__ x,
                  const float* __restrict__ Wq, const float* __restrict__ Wk,
                  const float* __restrict__ Wv, const float* __restrict__ Wo,
                  const float* __restrict__ W1, const float* __restrict__ W2,
                  const float* __restrict__ bq, const float* __restrict__ bk,
                  const float* __restrict__ bv,
                  __half* __restrict__ xh,
                  __half* __restrict__ wqkvt, __half* __restrict__ wot,
                  __half* __restrict__ w1t,   __half* __restrict__ w2t,
                  float* __restrict__ bqkv)
{
    const int bid = blockIdx.x;
    const int tid = threadIdx.x;

    if (bid < 3072) {
        const float* W; __half* Wt; int K, N, tile;
        if      (bid < 256)  { W = Wq; Wt = wqkvt;               K = Ds;  N = Ds;  tile = bid; }
        else if (bid < 512)  { W = Wk; Wt = wqkvt + Ds * Ds;     K = Ds;  N = Ds;  tile = bid - 256; }
        else if (bid < 768)  { W = Wv; Wt = wqkvt + 2 * Ds * Ds; K = Ds;  N = Ds;  tile = bid - 512; }
        else if (bid < 1024) { W = Wo; Wt = wot;                 K = Ds;  N = Ds;  tile = bid - 768; }
        else if (bid < 2048) { W = W1; Wt = w1t;                 K = Ds;  N = FFs; tile = bid - 1024; }
        else                 { W = W2; Wt = w2t;                 K = FFs; N = Ds;  tile = bid - 2048; }
        const int ntx = N / 32;
        const int nx = (tile % ntx) * 32, ky = (tile / ntx) * 32;

        __shared__ float t[32][33];
        const int xx = tid & 31, yy = tid >> 5;   // 32 x 8
#pragma unroll
        for (int j = 0; j < 32; j += 8)
            t[yy + j][xx] = W[(size_t)(ky + yy + j) * N + nx + xx];
        __syncthreads();
#pragma unroll
        for (int j = 0; j < 32; j += 8)
            Wt[(size_t)(nx + yy + j) * K + ky + xx] = __float2half(t[xx][yy + j]);
    } else if (bid < 4096) {
        // x -> half: 1,048,576 float4 total / 1024 blocks = 1024 per block
        const int base = (bid - 3072) * 1024;
#pragma unroll
        for (int it = 0; it < 4; it++) {
            int i = base + tid + it * 256;
            float4 v = ((const float4*)x)[i];
            __half2 lo = __floats2half2_rn(v.x, v.y);
            __half2 hi = __floats2half2_rn(v.z, v.w);
            ((uint2*)xh)[i] = make_uint2(*(uint32_t*)&lo, *(uint32_t*)&hi);
        }
    } else {
        for (int i = tid; i < QS; i += 256)
            bqkv[i] = (i < Ds) ? bq[i] : (i < 2 * Ds) ? bk[i - Ds] : bv[i - 2 * Ds];
    }
}

// ================= fp16 tensor-core GEMM (round-10 best) ====================
// C[M,N] = A[M,K] @ Bt[N,K]^T + bias.
// 256 thr, CTA tile 128x256x64, warp grid 2x4, warp tile 64x64.
// 3-stage cp.async pipeline, ldmatrix fragment loads.
// out_mode: 0 = fp32, 1 = fp32 rna-rounded, 2 = half
#define HST    72
#define HAS    (128 * HST)
#define HBS    (256 * HST)
#define HSTG   (HAS + HBS)
#define HG_SMEM (3 * HSTG * 2)

__global__ __launch_bounds__(256, 1)
void hgemm(const __half* __restrict__ A, const __half* __restrict__ Bt,
           const float* __restrict__ bias, void* __restrict__ Cv,
           int M, int N, int K, int relu, int out_mode)
{
    extern __shared__ __align__(256) __half sh[];
    const uint32_t sb = (uint32_t)__cvta_generic_to_shared(sh);

    const int tid  = threadIdx.x;
    const int lane = tid & 31;
    const int warp = tid >> 5;
    const int gid  = lane >> 2;
    const int tg   = lane & 3;
    const int wm   = (warp >> 2) * 64;
    const int wn   = (warp & 3) * 64;
    const int bm   = blockIdx.y * 128;
    const int bn   = blockIdx.x * 256;

    const int ar = tid >> 3;
    const int ac = (tid & 7) * 8;

    const int a_row = wm + ((lane >> 3) & 1) * 8 + (lane & 7);
    const int a_k   = ((lane >> 4) & 1) * 8;
    const int b_row = wn + ((lane >> 4) & 1) * 8 + (lane & 7);
    const int b_k   = ((lane >> 3) & 1) * 8;

    float d[4][8][4];
#pragma unroll
    for (int i = 0; i < 4; i++)
#pragma unroll
        for (int j = 0; j < 8; j++)
#pragma unroll
            for (int c = 0; c < 4; c++) d[i][j][c] = 0.f;

    auto do_load = [&](int stage, int k0) {
        const __half* pa = A  + (size_t)(bm + ar) * K + k0 + ac;
        const __half* pb = Bt + (size_t)(bn + ar) * K + k0 + ac;
        const uint32_t ba = sb + (uint32_t)stage * (HSTG * 2);
        const uint32_t bb = ba + HAS * 2;
#pragma unroll
        for (int i = 0; i < 4; i++) {
            uint32_t off = (uint32_t)((ar + 32 * i) * HST + ac) * 2;
            cp16(ba + off, pa + (size_t)32 * i * K);
        }
#pragma unroll
        for (int i = 0; i < 8; i++) {
            uint32_t off = (uint32_t)((ar + 32 * i) * HST + ac) * 2;
            cp16(bb + off, pb + (size_t)32 * i * K);
        }
    };

    const int T = K / 64;
    do_load(0, 0);
    CP_COMMIT();
    if (T > 1) { do_load(1, 64); CP_COMMIT(); }

    for (int t = 0; t < T; t++) {
        if (t + 1 < T) { CP_WAIT(1); } else { CP_WAIT(0); }
        __syncthreads();

        const int buf = t % 3;
        const uint32_t sA = sb + (uint32_t)buf * (HSTG * 2);
        const uint32_t sB = sA + HAS * 2;

#pragma unroll
        for (int kc = 0; kc < 4; kc++) {
            const int kk = kc * 16;
            uint32_t af[4][4], bf[4][4];
#pragma unroll
            for (int im = 0; im < 4; im++)
                ldsm_x4(af[im], sA + (uint32_t)((a_row + im * 16) * HST + kk + a_k) * 2);
#pragma unroll
            for (int jp = 0; jp < 4; jp++)
                ldsm_x4(bf[jp], sB + (uint32_t)((b_row + jp * 16) * HST + kk + b_k) * 2);
#pragma unroll
            for (int im = 0; im < 4; im++)
#pragma unroll
                for (int jn = 0; jn < 8; jn++)
                    mma_f16(d[im][jn], af[im][0], af[im][1], af[im][2], af[im][3],
                            bf[jn >> 1][(jn & 1) * 2], bf[jn >> 1][(jn & 1) * 2 + 1]);
        }

        if (t + 2 < T) { do_load((t + 2) % 3, (t + 2) * 64); CP_COMMIT(); }
    }

    // epilogue
#pragma unroll
    for (int jn = 0; jn < 8; jn++) {
        const int col = bn + wn + jn * 8 + 2 * tg;
        float2 bv = *(const float2*)&bias[col];
#pragma unroll
        for (int im = 0; im < 4; im++) {
            const int row = bm + wm + im * 16 + gid;
            float v0 = d[im][jn][0] + bv.x, v1 = d[im][jn][1] + bv.y;
            float v2 = d[im][jn][2] + bv.x, v3 = d[im][jn][3] + bv.y;
            if (relu) {
                v0 = fmaxf(v0, 0.f); v1 = fmaxf(v1, 0.f);
                v2 = fmaxf(v2, 0.f); v3 = fmaxf(v3, 0.f);
            }
            if (out_mode == 2) {
                __half* Ch = (__half*)Cv;
                *(__half2*)&Ch[(size_t)row       * N + col] = __floats2half2_rn(v0, v1);
                *(__half2*)&Ch[(size_t)(row + 8) * N + col] = __floats2half2_rn(v2, v3);
            } else {
                if (out_mode == 1) { v0 = rna(v0); v1 = rna(v1); v2 = rna(v2); v3 = rna(v3); }
                float* Cf = (float*)Cv;
                *(float2*)&Cf[(size_t)row       * N + col] = make_float2(v0, v1);
                *(float2*)&Cf[(size_t)(row + 8) * N + col] = make_float2(v2, v3);
            }
        }
    }
}

// ============== banded attention, full fp16 m16n8k16 (round-10 best) ========
#define AST 72
#define ATTN_SMEM (3 * 64 * AST * 2)

__global__ __launch_bounds__(128)
void attn_f16(const __half* __restrict__ qkv, __half* __restrict__ out)
{
    extern __shared__ __half smh[];
    __half (*Qs)[AST] = (__half(*)[AST])smh;                 // also Ps
    __half (*Ks)[AST] = (__half(*)[AST])(smh + 64 * AST);
    const uint32_t sbase = (uint32_t)__cvta_generic_to_shared(smh);
    const uint32_t sbK = sbase + 64 * AST * 2;
    const uint32_t sbV = sbase + 2 * 64 * AST * 2;

    const int bh   = blockIdx.y;
    const int b    = bh >> 3;
    const int h    = bh & 7;
    const int q0   = blockIdx.x * 64;
    const int tid  = threadIdx.x;
    const int lane = tid & 31;
    const int warp = tid >> 5;
    const int gid  = lane >> 2;
    const int tg   = lane & 3;
    const int wm   = warp * 16;

    const int sr = tid >> 3;
    const int sc = (tid & 7) * 8;

    {
        const __half* gq = qkv + ((size_t)(b * Ls + q0 + sr)) * QS + h * HDs + sc;
        const uint32_t dq = sbase + (uint32_t)(sr * AST + sc) * 2;
#pragma unroll
        for (int i = 0; i < 4; i++)
            cp16(dq + i * (16 * AST * 2), gq + (size_t)16 * i * QS);
    }
    CP_COMMIT();
    CP_WAIT(0);
    __syncthreads();

    uint32_t qa[4][4];
#pragma unroll
    for (int kc = 0; kc < 4; kc++) {
        const __half* p0 = &Qs[wm + gid    ][kc * 16 + 2 * tg];
        const __half* p1 = &Qs[wm + gid + 8][kc * 16 + 2 * tg];
        qa[kc][0] = *(const uint32_t*)p0;
        qa[kc][1] = *(const uint32_t*)p1;
        qa[kc][2] = *(const uint32_t*)(p0 + 8);
        qa[kc][3] = *(const uint32_t*)(p1 + 8);
    }

    float o[8][4];
#pragma unroll
    for (int jn = 0; jn < 8; jn++)
#pragma unroll
        for (int c = 0; c < 4; c++) o[jn][c] = 0.f;
    float m0 = -1e30f, m1 = -1e30f, l0 = 0.f, l1 = 0.f;

    const int row0 = q0 + wm + gid;
    const int row1 = row0 + 8;
    const int kstart = max(0, q0 - WIN);
    const int kend   = min(Ls, q0 + 64 + WIN);

    const int vkey = ((lane >> 3) & 1) * 8 + (lane & 7);
    const int vdim = ((lane >> 4) & 1) * 8;

    for (int kt = kstart; kt < kend; kt += 64) {
        __syncthreads();
        {
            const __half* gk = qkv + ((size_t)(b * Ls + kt + sr)) * QS + Ds     + h * HDs + sc;
            const __half* gv = qkv + ((size_t)(b * Ls + kt + sr)) * QS + 2 * Ds + h * HDs + sc;
            const uint32_t dk = sbK + (uint32_t)(sr * AST + sc) * 2;
            const uint32_t dv = sbV + (uint32_t)(sr * AST + sc) * 2;
#pragma unroll
            for (int i = 0; i < 4; i++) {
                cp16(dk + i * (16 * AST * 2), gk + (size_t)16 * i * QS);
                cp16(dv + i * (16 * AST * 2), gv + (size_t)16 * i * QS);
            }
        }
        CP_COMMIT();
        CP_WAIT(0);
        __syncthreads();

        float s[8][4];
#pragma unroll
        for (int jn = 0; jn < 8; jn++)
#pragma unroll
            for (int c = 0; c < 4; c++) s[jn][c] = 0.f;

#pragma unroll
        for (int kc = 0; kc < 4; kc++) {
#pragma unroll
            for (int jn = 0; jn < 8; jn++) {
                const __half* bp = &Ks[jn * 8 + gid][kc * 16 + 2 * tg];
                uint32_t b0 = *(const uint32_t*)bp;
                uint32_t b1 = *(const uint32_t*)(bp + 8);
                mma_f16(s[jn], qa[kc][0], qa[kc][1], qa[kc][2], qa[kc][3], b0, b1);
            }
        }

        float rmax0 = -1e30f, rmax1 = -1e30f;
#pragma unroll
        for (int jn = 0; jn < 8; jn++) {
            int cb = kt + jn * 8 + 2 * tg;
            s[jn][0] = (abs(cb     - row0) <= WIN) ? s[jn][0] * 0.125f : -1e30f;
            s[jn][1] = (abs(cb + 1 - row0) <= WIN) ? s[jn][1] * 0.125f : -1e30f;
            s[jn][2] = (abs(cb     - row1) <= WIN) ? s[jn][2] * 0.125f : -1e30f;
            s[jn][3] = (abs(cb + 1 - row1) <= WIN) ? s[jn][3] * 0.125f : -1e30f;
            rmax0 = fmaxf(rmax0, fmaxf(s[jn][0], s[jn][1]));
            rmax1 = fmaxf(rmax1, fmaxf(s[jn][2], s[jn][3]));
        }
        rmax0 = fmaxf(rmax0, __shfl_xor_sync(0xffffffffu, rmax0, 1));
        rmax0 = fmaxf(rmax0, __shfl_xor_sync(0xffffffffu, rmax0, 2));
        rmax1 = fmaxf(rmax1, __shfl_xor_sync(0xffffffffu, rmax1, 1));
        rmax1 = fmaxf(rmax1, __shfl_xor_sync(0xffffffffu, rmax1, 2));

        float mn0 = fmaxf(m0, rmax0);
        float mn1 = fmaxf(m1, rmax1);
        float sc0 = __expf(m0 - mn0);
        float sc1 = __expf(m1 - mn1);
        m0 = mn0; m1 = mn1;
        l0 *= sc0; l1 *= sc1;
#pragma unroll
        for (int jn = 0; jn < 8; jn++) {
            o[jn][0] *= sc0; o[jn][1] *= sc0;
            o[jn][2] *= sc1; o[jn][3] *= sc1;
        }

#pragma unroll
        for (int jn = 0; jn < 8; jn++) {
            float p0 = __expf(s[jn][0] - m0);
            float p1 = __expf(s[jn][1] - m0);
            float p2 = __expf(s[jn][2] - m1);
            float p3 = __expf(s[jn][3] - m1);
            l0 += p0 + p1;
            l1 += p2 + p3;
            *(__half2*)&Qs[wm + gid    ][jn * 8 + 2 * tg] = __floats2half2_rn(p0, p1);
            *(__half2*)&Qs[wm + gid + 8][jn * 8 + 2 * tg] = __floats2half2_rn(p2, p3);
        }
        __syncwarp();

#pragma unroll
        for (int kc = 0; kc < 4; kc++) {
            const __half* pp0 = &Qs[wm + gid    ][kc * 16 + 2 * tg];
            const __half* pp1 = &Qs[wm + gid + 8][kc * 16 + 2 * tg];
            uint32_t a0 = *(const uint32_t*)pp0;
            uint32_t a1 = *(const uint32_t*)pp1;
            uint32_t a2 = *(const uint32_t*)(pp0 + 8);
            uint32_t a3 = *(const uint32_t*)(pp1 + 8);
#pragma unroll
            for (int jp = 0; jp < 4; jp++) {
                uint32_t vaddr = sbV + (uint32_t)((kc * 16 + vkey) * AST + jp * 16 + vdim) * 2;
                uint32_t b0, b1, b2, b3;
                ldsm_x4_trans(b0, b1, b2, b3, vaddr);
                mma_f16(o[jp * 2    ], a0, a1, a2, a3, b0, b1);
                mma_f16(o[jp * 2 + 1], a0, a1, a2, a3, b2, b3);
            }
        }
    }

    l0 += __shfl_xor_sync(0xffffffffu, l0, 1);
    l0 += __shfl_xor_sync(0xffffffffu, l0, 2);
    l1 += __shfl_xor_sync(0xffffffffu, l1, 1);
    l1 += __shfl_xor_sync(0xffffffffu, l1, 2);
    const float inv0 = 1.f / l0;
    const float inv1 = 1.f / l1;

    __half* o0 = out + ((size_t)(b * Ls + row0)) * Ds + h * HDs;
    __half* o1 = out + ((size_t)(b * Ls + row1)) * Ds + h * HDs;
#pragma unroll
    for (int jn = 0; jn < 8; jn++) {
        int c = jn * 8 + 2 * tg;
        *(__half2*)&o0[c] = __floats2half2_rn(o[jn][0] * inv0, o[jn][1] * inv0);
        *(__half2*)&o1[c] = __floats2half2_rn(o[jn][2] * inv1, o[jn][3] * inv1);
    }
}

// ------- residual + LayerNorm: float4, 2 rows per 256-thread block ----------
__global__ __launch_bounds__(256)
void add_ln(const float* __restrict__ x, const float* __restrict__ r,
            const float* __restrict__ g, const float* __restrict__ bta,
            float* __restrict__ out, __half* __restrict__ out_r)
{
    const int half = threadIdx.x >> 7;            // 0 or 1 (row within block)
    const int row  = blockIdx.x * 2 + half;
    const int tid  = threadIdx.x & 127;           // lane within row group
    const int wid  = threadIdx.x >> 5;            // 0..7

    __shared__ float s1[8], s2[8];

    const float4* x4 = (const float4*)(x + (size_t)row * Ds);
    const float4* r4 = (const float4*)(r + (size_t)row * Ds);

    float4 u = x4[tid];
    float4 rv = r4[tid];
    u.x += rv.x; u.y += rv.y; u.z += rv.z; u.w += rv.w;
    float s  = u.x + u.y + u.z + u.w;
    float ss = u.x * u.x + u.y * u.y + u.z * u.z + u.w * u.w;
#pragma unroll
    for (int o = 16; o; o >>= 1) {
        s  += __shfl_xor_sync(0xffffffffu, s,  o);
        ss += __shfl_xor_sync(0xffffffffu, ss, o);
    }
    if ((threadIdx.x & 31) == 0) { s1[wid] = s; s2[wid] = ss; }
    __syncthreads();
    const int base = half * 4;
    float S  = s1[base] + s1[base + 1] + s1[base + 2] + s1[base + 3];
    float SS = s2[base] + s2[base + 1] + s2[base + 2] + s2[base + 3];
    float mu   = S * (1.f / Ds);
    float var  = SS * (1.f / Ds) - mu * mu;
    float rstd = rsqrtf(var + 1e-5f);

    float4 gv = ((const float4*)g)[tid];
    float4 bv = ((const float4*)bta)[tid];
    float4 val;
    val.x = (u.x - mu) * rstd * gv.x + bv.x;
    val.y = (u.y - mu) * rstd * gv.y + bv.y;
    val.z = (u.z - mu) * rstd * gv.z + bv.z;
    val.w = (u.w - mu) * rstd * gv.w + bv.w;
    ((float4*)(out + (size_t)row * Ds))[tid] = val;
    if (out_r) {
        __half2 lo = __floats2half2_rn(val.x, val.y);
        __half2 hi = __floats2half2_rn(val.z, val.w);
        ((uint2*)(out_r + (size_t)row * Ds))[tid] =
            make_uint2(*(uint32_t*)&lo, *(uint32_t*)&hi);
    }
}

// ---------------- launch ----------------------------------------------------
extern "C" void kernel_launch(void* const* d_in, const int* in_sizes, int n_in,
                              void* d_out, int out_size)
{
    const float* x    = (const float*)d_in[0];
    const float* Wq   = (const float*)d_in[1];
    const float* bq   = (const float*)d_in[2];
    const float* Wk   = (const float*)d_in[3];
    const float* bk   = (const float*)d_in[4];
    const float* Wv   = (const float*)d_in[5];
    const float* bv   = (const float*)d_in[6];
    const float* Wo   = (const float*)d_in[7];
    const float* bo   = (const float*)d_in[8];
    const float* ln1g = (const float*)d_in[9];
    const float* ln1b = (const float*)d_in[10];
    const float* W1   = (const float*)d_in[11];
    const float* b1   = (const float*)d_in[12];
    const float* W2   = (const float*)d_in[13];
    const float* b2   = (const float*)d_in[14];
    const float* ln2g = (const float*)d_in[15];
    const float* ln2b = (const float*)d_in[16];
    float* out = (float*)d_out;

    __half *xh, *qkv, *att, *hr, *ff1, *wqkvt, *wot, *w1t, *w2t;
    float  *prj, *h, *ff2, *bqkv;
    cudaGetSymbolAddress((void**)&xh,    g_xh);
    cudaGetSymbolAddress((void**)&qkv,   g_qkv);
    cudaGetSymbolAddress((void**)&att,   g_att);
    cudaGetSymbolAddress((void**)&prj,   g_prj);
    cudaGetSymbolAddress((void**)&h,     g_h);
    cudaGetSymbolAddress((void**)&hr,    g_hr);
    cudaGetSymbolAddress((void**)&ff1,   g_ff1);
    cudaGetSymbolAddress((void**)&ff2,   g_ff2);
    cudaGetSymbolAddress((void**)&wqkvt, g_wqkvt);
    cudaGetSymbolAddress((void**)&wot,   g_wot);
    cudaGetSymbolAddress((void**)&w1t,   g_w1t);
    cudaGetSymbolAddress((void**)&w2t,   g_w2t);
    cudaGetSymbolAddress((void**)&bqkv,  g_bqkv);

    cudaFuncSetAttribute(hgemm,    cudaFuncAttributeMaxDynamicSharedMemorySize, HG_SMEM);
    cudaFuncSetAttribute(attn_f16, cudaFuncAttributeMaxDynamicSharedMemorySize, ATTN_SMEM);

    // fused prologue: weight transposes + x->half + bias concat, one launch
    prologue_all<<<4097, 256>>>(x, Wq, Wk, Wv, Wo, W1, W2, bq, bk, bv,
                                xh, wqkvt, wot, w1t, w2t, bqkv);

    // fused QKV -> half
    hgemm<<<dim3(QS / 256, Ms / 128), 256, HG_SMEM>>>(xh, wqkvt, bqkv, qkv,
                                                      Ms, QS, Ds, 0, 2);

    attn_f16<<<dim3(Ls / 64, Bb * Hh), 128, ATTN_SMEM>>>(qkv, att);

    hgemm<<<dim3(Ds / 256, Ms / 128), 256, HG_SMEM>>>(att, wot, bo, prj,
                                                      Ms, Ds, Ds, 0, 0);
    add_ln<<<Ms / 2, 256>>>(x, prj, ln1g, ln1b, h, hr);

    hgemm<<<dim3(FFs / 256, Ms / 128), 256, HG_SMEM>>>(hr, w1t, b1, ff1,
                                                       Ms, FFs, Ds, 1, 2);
    hgemm<<<dim3(Ds / 256, Ms / 128), 256, HG_SMEM>>>(ff1, w2t, b2, ff2,
                                                      Ms, Ds, FFs, 0, 0);
    add_ln<<<Ms / 2, 256>>>(h, ff2, ln2g, ln2b, out, nullptr);
}